// round 3
// baseline (speedup 1.0000x reference)
#include <cuda_runtime.h>

// CostVolume2D: out[n, dy*9+dx, h, w] = mean_c f1[n,c,h,w] * f2pad[n,c,h+dy,w+dx]
// N=8, C=128, H=96, W=224, D=4 -> 81 channels. fp32.
//
// Strategy: 16x32 spatial tile per block, C staged through SMEM in chunks of 8.
// Each thread owns 4 x-pixels and accumulates 4*3*9=108 outputs in registers
// (the 9 dy offsets are split into 3 groups across gridDim.z to cap register
// pressure). z is ordered n-major so the 3x input re-read hits L2 (44 MB/batch
// fits the 126 MB L2).

#define N_ 8
#define C_ 128
#define H_ 96
#define W_ 224

constexpr int TH = 16;      // tile height (pixels)
constexpr int TW = 32;      // tile width  (pixels)
constexpr int PX = 4;       // x-pixels per thread
constexpr int DG = 3;       // dy offsets per block (9 split into 3 groups)
constexpr int CCH = 8;      // channels staged per SMEM chunk
constexpr int THREADS = 128; // blockDim = (8, 16)

__global__ __launch_bounds__(THREADS, 2)
void costvol_kernel(const float* __restrict__ f1,
                    const float* __restrict__ f2,
                    float* __restrict__ out)
{
    __shared__ float s1[CCH][TH][TW];          // f1 tile      : 16 KB
    __shared__ float s2[CCH][TH + 2][TW + 8];  // padded f2    : 23 KB

    const int tx  = threadIdx.x;           // 0..7
    const int ty  = threadIdx.y;           // 0..15
    const int tid = ty * 8 + tx;           // 0..127

    const int tile_x = blockIdx.x * TW;
    const int tile_y = blockIdx.y * TH;
    const int g      = blockIdx.z % 3;     // dy group
    const int n      = blockIdx.z / 3;     // batch (n-major for L2 locality)
    const int dy0    = 3 * g;

    const float* f1n = f1 + (size_t)n * C_ * H_ * W_;
    const float* f2n = f2 + (size_t)n * C_ * H_ * W_;

    float acc[PX][DG][9];
#pragma unroll
    for (int p = 0; p < PX; p++)
#pragma unroll
        for (int d = 0; d < DG; d++)
#pragma unroll
            for (int x = 0; x < 9; x++)
                acc[p][d][x] = 0.0f;

    for (int cb = 0; cb < C_; cb += CCH) {
        __syncthreads();  // smem safe to overwrite

        // ---- load f1 chunk: CCH*TH*TW floats = 1024 float4, 8 per thread ----
#pragma unroll
        for (int i = 0; i < (CCH * TH * TW / 4) / THREADS; i++) {
            int idx = tid + i * THREADS;   // 0..1023
            int c   = idx >> 7;            // /128 (float4s per channel)
            int rem = idx & 127;
            int r   = rem >> 3;            // row 0..15
            int q   = rem & 7;             // float4 col 0..7
            float4 v = *reinterpret_cast<const float4*>(
                f1n + ((size_t)(cb + c) * H_ + (tile_y + r)) * W_ + tile_x + q * 4);
            *reinterpret_cast<float4*>(&s1[c][r][q * 4]) = v;
        }

        // ---- load f2 chunk (zero-padded): CCH*18*40 = 5760 floats, 45/thread ----
        {
            constexpr int RW = TW + 8;                 // 40
            constexpr int PER_C = (TH + 2) * RW;       // 720
            constexpr int TOTAL = CCH * PER_C;         // 5760
            for (int idx = tid; idx < TOTAL; idx += THREADS) {
                int c   = idx / PER_C;
                int rem = idx - c * PER_C;
                int r   = rem / RW;
                int col = rem - r * RW;
                int gy  = tile_y + dy0 - 4 + r;
                int gx  = tile_x - 4 + col;
                float v = 0.0f;
                if ((unsigned)gy < (unsigned)H_ && (unsigned)gx < (unsigned)W_)
                    v = f2n[((size_t)(cb + c) * H_ + gy) * W_ + gx];
                s2[c][r][col] = v;
            }
        }
        __syncthreads();

        // ---- compute ----
#pragma unroll
        for (int c = 0; c < CCH; c++) {
            float a[PX];
            {
                float4 av = *reinterpret_cast<const float4*>(&s1[c][ty][tx * 4]);
                a[0] = av.x; a[1] = av.y; a[2] = av.z; a[3] = av.w;
            }
#pragma unroll
            for (int dyi = 0; dyi < DG; dyi++) {
                float r[12];
                const float* row = &s2[c][ty + dyi][tx * 4];
                float4 b0 = *reinterpret_cast<const float4*>(row);
                float4 b1 = *reinterpret_cast<const float4*>(row + 4);
                float4 b2 = *reinterpret_cast<const float4*>(row + 8);
                r[0] = b0.x; r[1]  = b0.y; r[2]  = b0.z; r[3]  = b0.w;
                r[4] = b1.x; r[5]  = b1.y; r[6]  = b1.z; r[7]  = b1.w;
                r[8] = b2.x; r[9]  = b2.y; r[10] = b2.z; r[11] = b2.w;
#pragma unroll
                for (int p = 0; p < PX; p++)
#pragma unroll
                    for (int dx = 0; dx < 9; dx++)
                        acc[p][dyi][dx] = fmaf(a[p], r[p + dx], acc[p][dyi][dx]);
            }
        }
    }

    // ---- epilogue: scale by 1/C, store float4 per (dyi,dx) ----
    const float inv = 1.0f / (float)C_;
    float* outn = out + (size_t)n * 81 * H_ * W_;
    const int y = tile_y + ty;
    const int x = tile_x + tx * 4;
#pragma unroll
    for (int dyi = 0; dyi < DG; dyi++)
#pragma unroll
        for (int dx = 0; dx < 9; dx++) {
            int k = (dy0 + dyi) * 9 + dx;
            float4 v = make_float4(acc[0][dyi][dx] * inv,
                                   acc[1][dyi][dx] * inv,
                                   acc[2][dyi][dx] * inv,
                                   acc[3][dyi][dx] * inv);
            *reinterpret_cast<float4*>(outn + ((size_t)k * H_ + y) * W_ + x) = v;
        }
}

extern "C" void kernel_launch(void* const* d_in, const int* in_sizes, int n_in,
                              void* d_out, int out_size)
{
    const float* f1 = (const float*)d_in[0];
    const float* f2 = (const float*)d_in[1];
    float* out = (float*)d_out;

    dim3 block(8, 16);                 // 128 threads
    dim3 grid(W_ / TW, H_ / TH, N_ * 3);  // 7 x 6 x 24 = 1008 blocks
    costvol_kernel<<<grid, block>>>(f1, f2, out);
}

// round 5
// speedup vs baseline: 3.0983x; 3.0983x over previous
#include <cuda_runtime.h>
#include <cstdint>

// CostVolume2D: out[n, dy*9+dx, h, w] = mean_c f1[n,c,h,w] * f2pad[n,c,h+dy,w+dx]
// N=8, C=128, H=96, W=224, D=4 -> 81 channels. fp32.
//
// R5: R4 design (cp.async double-buffered C-pipeline, CCH=4, depth 2; float4
// zfill staging; 3 CTAs/SM) with the chunk->channel addressing bug fixed:
// stage(cb) must offset by cb*CCH channels, not cb.

#define N_ 8
#define C_ 128
#define H_ 96
#define W_ 224

constexpr int TH = 16;        // tile height
constexpr int TW = 32;        // tile width
constexpr int PX = 4;         // x-pixels per thread
constexpr int DG = 3;         // dy offsets per block (9 split across gridDim.z)
constexpr int CCH = 4;        // channels per pipeline stage
constexpr int NCHUNK = C_ / CCH;   // 32
constexpr int THREADS = 128;  // blockDim = (8,16)
constexpr int RW  = TW + 8;   // 40 padded row
constexpr int S2R = TH + 2;   // 18 rows (covers 3 dy)
constexpr int F2_F4 = CCH * S2R * (RW / 4);  // 720 float4 per stage
constexpr int F1_F4 = CCH * TH * (TW / 4);   // 512 float4 per stage

__device__ __forceinline__ void cp_async16(uint32_t dst, const void* src, bool pred) {
    int sz = pred ? 16 : 0;
    asm volatile("cp.async.cg.shared.global [%0], [%1], 16, %2;\n"
                 :: "r"(dst), "l"(src), "r"(sz));
}
__device__ __forceinline__ void cp_commit() {
    asm volatile("cp.async.commit_group;\n" ::);
}
__device__ __forceinline__ void cp_wait1() {
    asm volatile("cp.async.wait_group 1;\n" ::);
}

__global__ __launch_bounds__(THREADS, 3)
void costvol_kernel(const float* __restrict__ f1,
                    const float* __restrict__ f2,
                    float* __restrict__ out)
{
    __shared__ __align__(16) float s1[2][CCH][TH][TW];   // 16 KB
    __shared__ __align__(16) float s2[2][CCH][S2R][RW];  // 23 KB

    const int tx  = threadIdx.x;          // 0..7
    const int ty  = threadIdx.y;          // 0..15
    const int tid = ty * 8 + tx;

    const int tile_x = blockIdx.x * TW;
    const int tile_y = blockIdx.y * TH;
    const int g      = blockIdx.z % 3;
    const int n      = blockIdx.z / 3;    // n-major z: consecutive blocks share batch (L2)
    const int dy0    = 3 * g;

    const float* f1n = f1 + (size_t)n * C_ * H_ * W_;
    const float* f2n = f2 + (size_t)n * C_ * H_ * W_;

    const uint32_t s1b = (uint32_t)__cvta_generic_to_shared(&s1[0][0][0][0]);
    const uint32_t s2b = (uint32_t)__cvta_generic_to_shared(&s2[0][0][0][0]);

    // ---- precompute chunk-invariant f2 staging descriptors (6 f4/thread) ----
    int  off2[6];     // float offset into the chunk's channel block of f2
    int  sm2[6];      // byte offset within one s2 buffer
    bool pr2[6];      // zfill predicate
    bool act2[6];     // thread participates
#pragma unroll
    for (int i = 0; i < 6; i++) {
        int idx = tid + THREADS * i;
        act2[i] = (idx < F2_F4);
        int id  = act2[i] ? idx : 0;
        int c   = id / (S2R * RW / 4);            // local channel 0..3
        int rem = id - c * (S2R * RW / 4);
        int r   = rem / (RW / 4);                 // padded row 0..17
        int q   = rem - r * (RW / 4);             // float4 col 0..9
        int gy  = tile_y + dy0 - 4 + r;
        bool valid = ((unsigned)gy < (unsigned)H_)
                   && !(q == 0 && tile_x == 0)
                   && !(q == (RW / 4 - 1) && tile_x + TW + 4 > W_);
        int gyc = valid ? gy : 0;
        off2[i] = (c * H_ + gyc) * W_ + tile_x - 4 + q * 4;
        if (q == 0 && tile_x == 0) off2[i] += 4;  // keep pointer in-bounds (unread, sz=0)
        sm2[i]  = ((c * S2R + r) * RW + q * 4) * 4;
        pr2[i]  = valid;
    }

    float acc[PX][DG][9];
#pragma unroll
    for (int p = 0; p < PX; p++)
#pragma unroll
        for (int d = 0; d < DG; d++)
#pragma unroll
            for (int x = 0; x < 9; x++)
                acc[p][d][x] = 0.0f;

    // ---- staging: chunk index cb stages channels [cb*CCH, cb*CCH+CCH) ----
    auto stage = [&](int buf, int cb) {
        const float* f1c = f1n + (size_t)cb * CCH * H_ * W_;   // FIX: *CCH
        const float* f2c = f2n + (size_t)cb * CCH * H_ * W_;   // FIX: *CCH
        uint32_t d1 = s1b + (uint32_t)buf * (CCH * TH * TW * 4);
        uint32_t d2 = s2b + (uint32_t)buf * (CCH * S2R * RW * 4);
        // f1: 512 f4 / 128 thr = 4 each, shift/mask indexing
#pragma unroll
        for (int i = 0; i < F1_F4 / THREADS; i++) {
            int idx = tid + THREADS * i;
            int c   = idx >> 7;
            int rem = idx & 127;
            int r   = rem >> 3;
            int q   = rem & 7;
            cp_async16(d1 + (uint32_t)(((c * TH + r) * TW + q * 4) * 4),
                       f1c + ((size_t)c * H_ + tile_y + r) * W_ + tile_x + q * 4,
                       true);
        }
        // f2: 720 f4, precomputed descriptors
#pragma unroll
        for (int i = 0; i < 6; i++) {
            if (act2[i])
                cp_async16(d2 + (uint32_t)sm2[i], f2c + off2[i], pr2[i]);
        }
    };

    // ---- pipeline prologue ----
    stage(0, 0); cp_commit();
    stage(1, 1); cp_commit();

    for (int cb = 0; cb < NCHUNK; cb++) {
        cp_wait1();            // chunk cb's group complete (<=1 group pending)
        __syncthreads();

        const int buf = cb & 1;
#pragma unroll
        for (int c = 0; c < CCH; c++) {
            float a[PX];
            {
                float4 av = *reinterpret_cast<const float4*>(&s1[buf][c][ty][tx * 4]);
                a[0] = av.x; a[1] = av.y; a[2] = av.z; a[3] = av.w;
            }
#pragma unroll
            for (int dyi = 0; dyi < DG; dyi++) {
                float r[12];
                const float* row = &s2[buf][c][ty + dyi][tx * 4];
                float4 b0 = *reinterpret_cast<const float4*>(row);
                float4 b1 = *reinterpret_cast<const float4*>(row + 4);
                float4 b2 = *reinterpret_cast<const float4*>(row + 8);
                r[0] = b0.x; r[1]  = b0.y; r[2]  = b0.z; r[3]  = b0.w;
                r[4] = b1.x; r[5]  = b1.y; r[6]  = b1.z; r[7]  = b1.w;
                r[8] = b2.x; r[9]  = b2.y; r[10] = b2.z; r[11] = b2.w;
#pragma unroll
                for (int p = 0; p < PX; p++)
#pragma unroll
                    for (int dx = 0; dx < 9; dx++)
                        acc[p][dyi][dx] = fmaf(a[p], r[p + dx], acc[p][dyi][dx]);
            }
        }

        __syncthreads();       // all threads done reading buf before restaging it
        if (cb + 2 < NCHUNK) stage(buf, cb + 2);
        cp_commit();           // uniform group count (possibly empty group)
    }

    // ---- epilogue ----
    const float inv = 1.0f / (float)C_;
    float* outn = out + (size_t)n * 81 * H_ * W_;
    const int y = tile_y + ty;
    const int x = tile_x + tx * 4;
#pragma unroll
    for (int dyi = 0; dyi < DG; dyi++)
#pragma unroll
        for (int dx = 0; dx < 9; dx++) {
            int k = (dy0 + dyi) * 9 + dx;
            float4 v = make_float4(acc[0][dyi][dx] * inv,
                                   acc[1][dyi][dx] * inv,
                                   acc[2][dyi][dx] * inv,
                                   acc[3][dyi][dx] * inv);
            *reinterpret_cast<float4*>(outn + ((size_t)k * H_ + y) * W_ + x) = v;
        }
}

extern "C" void kernel_launch(void* const* d_in, const int* in_sizes, int n_in,
                              void* d_out, int out_size)
{
    const float* f1 = (const float*)d_in[0];
    const float* f2 = (const float*)d_in[1];
    float* out = (float*)d_out;

    dim3 block(8, 16);
    dim3 grid(W_ / TW, H_ / TH, N_ * 3);   // 7 x 6 x 24
    costvol_kernel<<<grid, block>>>(f1, f2, out);
}

// round 8
// speedup vs baseline: 3.6687x; 1.1841x over previous
#include <cuda_runtime.h>
#include <cstdint>

// CostVolume2D: out[n, dy*9+dx, h, w] = mean_c f1[n,c,h,w] * f2pad[n,c,h+dy,w+dx]
// N=8, C=128, H=96, W=224, D=4 -> 81 channels. fp32.
//
// R6: R5 pipeline (cp.async double-buffered C-chunks, CCH=4, depth 2, 3 CTAs/SM)
// with the inner product rewritten as packed fma.rn.f32x2 (FFMA2):
// accumulators paired across the pixel dimension, r-operand pairs built once
// per (c,dyi) (6 natural even pairs + 5 mov.b64 odd pairs). 36 FFMA -> 18 FFMA2.

#define N_ 8
#define C_ 128
#define H_ 96
#define W_ 224

constexpr int TH = 16;
constexpr int TW = 32;
constexpr int DG = 3;         // dy offsets per block (9 split across gridDim.z)
constexpr int CCH = 4;        // channels per pipeline stage
constexpr int NCHUNK = C_ / CCH;   // 32
constexpr int THREADS = 128;  // blockDim = (8,16)
constexpr int RW  = TW + 8;   // 40 padded row
constexpr int S2R = TH + 2;   // 18 rows
constexpr int F2_F4 = CCH * S2R * (RW / 4);  // 720 float4 per stage
constexpr int F1_F4 = CCH * TH * (TW / 4);   // 512 float4 per stage

__device__ __forceinline__ void cp_async16(uint32_t dst, const void* src, bool pred) {
    int sz = pred ? 16 : 0;
    asm volatile("cp.async.cg.shared.global [%0], [%1], 16, %2;\n"
                 :: "r"(dst), "l"(src), "r"(sz));
}
__device__ __forceinline__ void cp_commit() {
    asm volatile("cp.async.commit_group;\n" ::);
}
__device__ __forceinline__ void cp_wait1() {
    asm volatile("cp.async.wait_group 1;\n" ::);
}

// packed f32x2 helpers
__device__ __forceinline__ uint64_t pk(float lo, float hi) {
    uint64_t r; asm("mov.b64 %0, {%1, %2};" : "=l"(r) : "f"(lo), "f"(hi)); return r;
}
__device__ __forceinline__ void fma2(uint64_t& acc, uint64_t a, uint64_t b) {
    asm("fma.rn.f32x2 %0, %1, %2, %0;" : "+l"(acc) : "l"(a), "l"(b));
}
__device__ __forceinline__ void upk(uint64_t v, float& lo, float& hi) {
    asm("mov.b64 {%0, %1}, %2;" : "=f"(lo), "=f"(hi) : "l"(v));
}

__global__ __launch_bounds__(THREADS, 3)
void costvol_kernel(const float* __restrict__ f1,
                    const float* __restrict__ f2,
                    float* __restrict__ out)
{
    __shared__ __align__(16) float s1[2][CCH][TH][TW];   // 16 KB
    __shared__ __align__(16) float s2[2][CCH][S2R][RW];  // 23 KB

    const int tx  = threadIdx.x;          // 0..7
    const int ty  = threadIdx.y;          // 0..15
    const int tid = ty * 8 + tx;

    const int tile_x = blockIdx.x * TW;
    const int tile_y = blockIdx.y * TH;
    const int g      = blockIdx.z % 3;
    const int n      = blockIdx.z / 3;    // n-major z for L2 locality
    const int dy0    = 3 * g;

    const float* f1n = f1 + (size_t)n * C_ * H_ * W_;
    const float* f2n = f2 + (size_t)n * C_ * H_ * W_;

    const uint32_t s1b = (uint32_t)__cvta_generic_to_shared(&s1[0][0][0][0]);
    const uint32_t s2b = (uint32_t)__cvta_generic_to_shared(&s2[0][0][0][0]);

    // ---- chunk-invariant f2 staging descriptors (6 f4/thread) ----
    int  off2[6];
    int  sm2[6];
    bool pr2[6];
    bool act2[6];
#pragma unroll
    for (int i = 0; i < 6; i++) {
        int idx = tid + THREADS * i;
        act2[i] = (idx < F2_F4);
        int id  = act2[i] ? idx : 0;
        int c   = id / (S2R * RW / 4);
        int rem = id - c * (S2R * RW / 4);
        int r   = rem / (RW / 4);
        int q   = rem - r * (RW / 4);
        int gy  = tile_y + dy0 - 4 + r;
        bool valid = ((unsigned)gy < (unsigned)H_)
                   && !(q == 0 && tile_x == 0)
                   && !(q == (RW / 4 - 1) && tile_x + TW + 4 > W_);
        int gyc = valid ? gy : 0;
        off2[i] = (c * H_ + gyc) * W_ + tile_x - 4 + q * 4;
        if (q == 0 && tile_x == 0) off2[i] += 4;  // keep ptr in-bounds (unread, sz=0)
        sm2[i]  = ((c * S2R + r) * RW + q * 4) * 4;
        pr2[i]  = valid;
    }

    // packed accumulators: [pp][dyi][dx], pp=0 -> pixels (0,1), pp=1 -> (2,3)
    uint64_t acc[2][DG][9];
#pragma unroll
    for (int pp = 0; pp < 2; pp++)
#pragma unroll
        for (int d = 0; d < DG; d++)
#pragma unroll
            for (int x = 0; x < 9; x++)
                acc[pp][d][x] = 0ull;

    auto stage = [&](int buf, int cb) {
        const float* f1c = f1n + (size_t)cb * CCH * H_ * W_;
        const float* f2c = f2n + (size_t)cb * CCH * H_ * W_;
        uint32_t d1 = s1b + (uint32_t)buf * (CCH * TH * TW * 4);
        uint32_t d2 = s2b + (uint32_t)buf * (CCH * S2R * RW * 4);
#pragma unroll
        for (int i = 0; i < F1_F4 / THREADS; i++) {
            int idx = tid + THREADS * i;
            int c   = idx >> 7;
            int rem = idx & 127;
            int r   = rem >> 3;
            int q   = rem & 7;
            cp_async16(d1 + (uint32_t)(((c * TH + r) * TW + q * 4) * 4),
                       f1c + ((size_t)c * H_ + tile_y + r) * W_ + tile_x + q * 4,
                       true);
        }
#pragma unroll
        for (int i = 0; i < 6; i++) {
            if (act2[i])
                cp_async16(d2 + (uint32_t)sm2[i], f2c + off2[i], pr2[i]);
        }
    };

    // ---- pipeline prologue ----
    stage(0, 0); cp_commit();
    stage(1, 1); cp_commit();

    for (int cb = 0; cb < NCHUNK; cb++) {
        cp_wait1();
        __syncthreads();

        const int buf = cb & 1;
#pragma unroll
        for (int c = 0; c < CCH; c++) {
            uint64_t a01, a23;
            {
                float4 av = *reinterpret_cast<const float4*>(&s1[buf][c][ty][tx * 4]);
                a01 = pk(av.x, av.y);
                a23 = pk(av.z, av.w);
            }
#pragma unroll
            for (int dyi = 0; dyi < DG; dyi++) {
                const float* row = &s2[buf][c][ty + dyi][tx * 4];
                float4 b0 = *reinterpret_cast<const float4*>(row);
                float4 b1 = *reinterpret_cast<const float4*>(row + 4);
                float4 b2 = *reinterpret_cast<const float4*>(row + 8);
                // even pairs (natural register pairs from the float4 loads)
                uint64_t pe0 = pk(b0.x, b0.y);
                uint64_t pe1 = pk(b0.z, b0.w);
                uint64_t pe2 = pk(b1.x, b1.y);
                uint64_t pe3 = pk(b1.z, b1.w);
                uint64_t pe4 = pk(b2.x, b2.y);
                uint64_t pe5 = pk(b2.z, b2.w);
                // odd pairs (cross-pair packs)
                uint64_t po0 = pk(b0.y, b0.z);
                uint64_t po1 = pk(b0.w, b1.x);
                uint64_t po2 = pk(b1.y, b1.z);
                uint64_t po3 = pk(b1.w, b2.x);
                uint64_t po4 = pk(b2.y, b2.z);

                // pair(k) = (r[k], r[k+1]); pp=0 uses pair(dx), pp=1 uses pair(dx+2)
                uint64_t pr[11] = {pe0, po0, pe1, po1, pe2, po2,
                                   pe3, po3, pe4, po4, pe5};
#pragma unroll
                for (int dx = 0; dx < 9; dx++) {
                    fma2(acc[0][dyi][dx], a01, pr[dx]);
                    fma2(acc[1][dyi][dx], a23, pr[dx + 2]);
                }
            }
        }

        __syncthreads();
        if (cb + 2 < NCHUNK) stage(buf, cb + 2);
        cp_commit();
    }

    // ---- epilogue ----
    const float inv = 1.0f / (float)C_;
    float* outn = out + (size_t)n * 81 * H_ * W_;
    const int y = tile_y + ty;
    const int x = tile_x + tx * 4;
#pragma unroll
    for (int dyi = 0; dyi < DG; dyi++)
#pragma unroll
        for (int dx = 0; dx < 9; dx++) {
            int k = (dy0 + dyi) * 9 + dx;
            float v0, v1, v2, v3;
            upk(acc[0][dyi][dx], v0, v1);
            upk(acc[1][dyi][dx], v2, v3);
            float4 v = make_float4(v0 * inv, v1 * inv, v2 * inv, v3 * inv);
            *reinterpret_cast<float4*>(outn + ((size_t)k * H_ + y) * W_ + x) = v;
        }
}

extern "C" void kernel_launch(void* const* d_in, const int* in_sizes, int n_in,
                              void* d_out, int out_size)
{
    const float* f1 = (const float*)d_in[0];
    const float* f2 = (const float*)d_in[1];
    float* out = (float*)d_out;

    dim3 block(8, 16);
    dim3 grid(W_ / TW, H_ / TH, N_ * 3);   // 7 x 6 x 24
    costvol_kernel<<<grid, block>>>(f1, f2, out);
}